// round 4
// baseline (speedup 1.0000x reference)
#include <cuda_runtime.h>
#include <cuda_fp16.h>
#include <cstdint>

// QueryConditionedRouter via mma.sync (HMMA) fp16 2-term split, 3 passes.
// R4: warp M-tile doubled to 32 rows so each B-fragment load feeds 2 m-tiles
//     (B was 4/5 of L1 traffic at 8x replication per block).
//   vis_emb  : (128, 576, 1024) f32  -> M = 73728 rows, K = 1024
//   query_emb: (8, 1024) f32
//   W_gate   : (64, 2048) f32  (W_vis = [:, :1024], W_qry = [:, 1024:])
// Output (concat f32): topk_scores (M,2) | topk_idx (M,2) | gate_scores (M,64) | gate_logits (M,64)

#define MROWS   73728
#define KDIM    1024
#define NEXP    64
#define NBLOCKS (MROWS / 128)   // 576, 128 rows per 128-thread block (4 warps x 32 rows)
#define ASCALE  4096.0f         // 2^12
#define BSCALE  32.0f           // 2^5
#define OSCALE  7.62939453125e-06f  // 2^-17

__device__ float g_qlog[512];
// B fragments, fragment-major: entry = ((chunk*8 + ntile)*32 + lane)
//   uint4 = { hi(k0,k1), hi(k8,k9), lo(k0,k1), lo(k8,k9) }  (fp16x2 packed)
__device__ uint4 g_bfrag[64 * 8 * 32];

__device__ __forceinline__ void split_pair(float f0, float f1, uint32_t &h, uint32_t &l) {
    __half2 hh = __floats2half2_rn(f0, f1);
    float g0 = __low2float(hh), g1 = __high2float(hh);
    __half2 ll = __floats2half2_rn(f0 - g0, f1 - g1);
    h = *reinterpret_cast<uint32_t*>(&hh);
    l = *reinterpret_cast<uint32_t*>(&ll);
}

__device__ __forceinline__ void mma16816(float* c, uint32_t a0, uint32_t a1, uint32_t a2,
                                         uint32_t a3, uint32_t b0, uint32_t b1) {
    asm volatile(
        "mma.sync.aligned.m16n8k16.row.col.f32.f16.f16.f32 "
        "{%0,%1,%2,%3}, {%4,%5,%6,%7}, {%8,%9}, {%0,%1,%2,%3};"
        : "+f"(c[0]), "+f"(c[1]), "+f"(c[2]), "+f"(c[3])
        : "r"(a0), "r"(a1), "r"(a2), "r"(a3), "r"(b0), "r"(b1));
}

// ---------------------------------------------------------------------------
// Prep: (a) qry logits (one warp per (b,e)); (b) B fragment build.
// ---------------------------------------------------------------------------
__global__ void qcr_prep_kernel(const float* __restrict__ qry, const float* __restrict__ Wg) {
    const int tid = blockIdx.x * 256 + threadIdx.x;
    {
        int w = tid >> 5, lane = tid & 31;
        const float* qp = qry + (size_t)(w >> 6) * KDIM;
        const float* wp = Wg + (size_t)(w & 63) * 2048 + 1024;
        float acc = 0.f;
        #pragma unroll 8
        for (int i = lane; i < KDIM; i += 32) acc += qp[i] * wp[i];
        #pragma unroll
        for (int o = 16; o; o >>= 1) acc += __shfl_xor_sync(0xffffffffu, acc, o);
        if (lane == 0) g_qlog[w] = acc;
    }
    {
        int lane = tid & 31;
        int t = (tid >> 5) & 7;
        int c = tid >> 8;
        int n = t * 8 + (lane >> 2);
        int k0 = c * 16 + (lane & 3) * 2;
        const float* wr = Wg + (size_t)n * 2048 + k0;
        float w0 = wr[0] * BSCALE, w1 = wr[1] * BSCALE;
        float w8 = wr[8] * BSCALE, w9 = wr[9] * BSCALE;
        uint4 v;
        split_pair(w0, w1, v.x, v.z);
        split_pair(w8, w9, v.y, v.w);
        g_bfrag[tid] = v;
    }
}

// ---------------------------------------------------------------------------
// Main: 576 blocks x 128 threads (4 warps). Warp w: rows [rowbase+32w, +32),
// all 64 experts. 2 m-tiles share each B-fragment load.
// ---------------------------------------------------------------------------
__global__ void __launch_bounds__(128, 2) qcr_main_kernel(
    const float* __restrict__ vis,
    float* __restrict__ out)
{
    __shared__ float Ls[128 * 65];
    __shared__ float qrow[64];

    const int tid = threadIdx.x;
    const int warp = tid >> 5;
    const int lane = tid & 31;
    const int grp = lane >> 2;        // 0..7
    const int tig = lane & 3;         // 0..3
    const int rowbase = blockIdx.x * 128;

    if (tid < 64) qrow[tid] = g_qlog[(rowbase / 9216) * 64 + tid];

    const int r0 = rowbase + warp * 32 + grp;
    const float2* Ar[4];
    #pragma unroll
    for (int rr = 0; rr < 4; rr++)
        Ar[rr] = reinterpret_cast<const float2*>(vis + (size_t)(r0 + 8 * rr) * KDIM) + tig;
    const uint4* Bf = g_bfrag + lane;

    float acc[2][8][4];
    #pragma unroll
    for (int i = 0; i < 2; i++)
        #pragma unroll
        for (int t = 0; t < 8; t++)
            #pragma unroll
            for (int j = 0; j < 4; j++) acc[i][t][j] = 0.f;

    #pragma unroll 2
    for (int c = 0; c < 64; c++) {
        // A: 4 rows x (k01, k89) pairs
        float2 p[4][2];
        #pragma unroll
        for (int rr = 0; rr < 4; rr++) {
            p[rr][0] = Ar[rr][c * 8];
            p[rr][1] = Ar[rr][c * 8 + 4];
        }
        uint32_t ah[4][2], al[4][2];
        #pragma unroll
        for (int rr = 0; rr < 4; rr++) {
            split_pair(p[rr][0].x * ASCALE, p[rr][0].y * ASCALE, ah[rr][0], al[rr][0]);
            split_pair(p[rr][1].x * ASCALE, p[rr][1].y * ASCALE, ah[rr][1], al[rr][1]);
        }

        #pragma unroll
        for (int t = 0; t < 8; t++) {
            uint4 b = Bf[(c * 8 + t) * 32];
            #pragma unroll
            for (int i = 0; i < 2; i++) {
                // a-frag rows rr = 2i, 2i+1
                mma16816(acc[i][t], ah[2*i][0], ah[2*i+1][0], ah[2*i][1], ah[2*i+1][1], b.x, b.y);
                mma16816(acc[i][t], ah[2*i][0], ah[2*i+1][0], ah[2*i][1], ah[2*i+1][1], b.z, b.w);
                mma16816(acc[i][t], al[2*i][0], al[2*i+1][0], al[2*i][1], al[2*i+1][1], b.x, b.y);
            }
        }
    }

    // ---- stage logits to smem (rescale + add query logits) ----
    #pragma unroll
    for (int i = 0; i < 2; i++) {
        const int rl0 = warp * 32 + i * 16 + grp;
        #pragma unroll
        for (int t = 0; t < 8; t++) {
            int col = t * 8 + tig * 2;
            float q0 = qrow[col], q1 = qrow[col + 1];
            Ls[rl0 * 65 + col]           = acc[i][t][0] * OSCALE + q0;
            Ls[rl0 * 65 + col + 1]       = acc[i][t][1] * OSCALE + q1;
            Ls[(rl0 + 8) * 65 + col]     = acc[i][t][2] * OSCALE + q0;
            Ls[(rl0 + 8) * 65 + col + 1] = acc[i][t][3] * OSCALE + q1;
        }
    }
    __syncthreads();

    // ---- per-row softmax + top-2 + outputs (thread = row) ----
    const size_t O_TI = 2 * (size_t)MROWS;
    const size_t O_SC = 4 * (size_t)MROWS;
    const size_t O_LG = O_SC + (size_t)MROWS * NEXP;

    {
        float d[64];
        const float* Lr = Ls + tid * 65;
        #pragma unroll
        for (int e = 0; e < 64; e++) d[e] = Lr[e];

        float m1 = -1e30f, m2 = -1e30f;
        int i1 = 0, i2 = 0;
        #pragma unroll
        for (int e = 0; e < 64; e++) {
            float v = d[e];
            if (v > m1) { m2 = m1; i2 = i1; m1 = v; i1 = e; }
            else if (v > m2) { m2 = v; i2 = e; }
        }
        float ssum = 0.f;
        #pragma unroll
        for (int e = 0; e < 64; e++) ssum += __expf(d[e] - m1);
        float inv = 1.0f / ssum;

        size_t g = (size_t)(rowbase + tid);
        out[g * 2 + 0] = inv;
        out[g * 2 + 1] = __expf(m2 - m1) * inv;
        out[O_TI + g * 2 + 0] = (float)i1;
        out[O_TI + g * 2 + 1] = (float)i2;

        float4* sc = reinterpret_cast<float4*>(out + O_SC + g * 64);
        float4* lg = reinterpret_cast<float4*>(out + O_LG + g * 64);
        #pragma unroll
        for (int e4 = 0; e4 < 16; e4++) {
            float4 lv = make_float4(d[e4 * 4], d[e4 * 4 + 1], d[e4 * 4 + 2], d[e4 * 4 + 3]);
            lg[e4] = lv;
            sc[e4] = make_float4(__expf(lv.x - m1) * inv, __expf(lv.y - m1) * inv,
                                 __expf(lv.z - m1) * inv, __expf(lv.w - m1) * inv);
        }
    }
}

// ---------------------------------------------------------------------------
extern "C" void kernel_launch(void* const* d_in, const int* in_sizes, int n_in,
                              void* d_out, int out_size)
{
    const float* vis = (const float*)d_in[0];
    const float* qry = (const float*)d_in[1];
    const float* Wg  = (const float*)d_in[2];
    float* out = (float*)d_out;

    qcr_prep_kernel<<<64, 256>>>(qry, Wg);
    qcr_main_kernel<<<NBLOCKS, 128>>>(vis, out);
}

// round 5
// speedup vs baseline: 1.0279x; 1.0279x over previous
#include <cuda_runtime.h>
#include <cuda_fp16.h>
#include <cstdint>

// QueryConditionedRouter via mma.sync (HMMA) fp16 2-term split, 3 passes.
// R5: warp tile 32 rows x 32 experts (B bytes/lane halved, acc regs unchanged);
//     A staged through smem via cp.async (full-line wavefronts, no duplication).
//   vis_emb  : (128, 576, 1024) f32  -> M = 73728 rows, K = 1024
//   query_emb: (8, 1024) f32
//   W_gate   : (64, 2048) f32
// Output (concat f32): topk_scores (M,2) | topk_idx (M,2) | gate_scores (M,64) | gate_logits (M,64)

#define MROWS   73728
#define KDIM    1024
#define NEXP    64
#define NBLOCKS (MROWS / 128)       // 576
#define NSTAGE  32                  // k32 slabs
#define ASTRIDE 36                  // padded floats per A smem row (<=2-way LDS.64)
#define ASCALE  4096.0f             // 2^12
#define BSCALE  32.0f               // 2^5
#define OSCALE  7.62939453125e-06f  // 2^-17

__device__ float g_qlog[512];
// B fragments, fragment-major: entry = ((chunk*8 + ntile)*32 + lane)
//   uint4 = { hi(k0,k1), hi(k8,k9), lo(k0,k1), lo(k8,k9) }
__device__ uint4 g_bfrag[64 * 8 * 32];

__device__ __forceinline__ void split_pair(float f0, float f1, uint32_t &h, uint32_t &l) {
    __half2 hh = __floats2half2_rn(f0, f1);
    float g0 = __low2float(hh), g1 = __high2float(hh);
    __half2 ll = __floats2half2_rn(f0 - g0, f1 - g1);
    h = *reinterpret_cast<uint32_t*>(&hh);
    l = *reinterpret_cast<uint32_t*>(&ll);
}

__device__ __forceinline__ void mma16816(float* c, uint32_t a0, uint32_t a1, uint32_t a2,
                                         uint32_t a3, uint32_t b0, uint32_t b1) {
    asm volatile(
        "mma.sync.aligned.m16n8k16.row.col.f32.f16.f16.f32 "
        "{%0,%1,%2,%3}, {%4,%5,%6,%7}, {%8,%9}, {%0,%1,%2,%3};"
        : "+f"(c[0]), "+f"(c[1]), "+f"(c[2]), "+f"(c[3])
        : "r"(a0), "r"(a1), "r"(a2), "r"(a3), "r"(b0), "r"(b1));
}

__device__ __forceinline__ void cp16(uint32_t s, const float* g) {
    asm volatile("cp.async.cg.shared.global [%0], [%1], 16;" :: "r"(s), "l"(g));
}

// ---------------------------------------------------------------------------
__global__ void qcr_prep_kernel(const float* __restrict__ qry, const float* __restrict__ Wg) {
    const int tid = blockIdx.x * 256 + threadIdx.x;
    {
        int w = tid >> 5, lane = tid & 31;
        const float* qp = qry + (size_t)(w >> 6) * KDIM;
        const float* wp = Wg + (size_t)(w & 63) * 2048 + 1024;
        float acc = 0.f;
        #pragma unroll 8
        for (int i = lane; i < KDIM; i += 32) acc += qp[i] * wp[i];
        #pragma unroll
        for (int o = 16; o; o >>= 1) acc += __shfl_xor_sync(0xffffffffu, acc, o);
        if (lane == 0) g_qlog[w] = acc;
    }
    {
        int lane = tid & 31;
        int t = (tid >> 5) & 7;
        int c = tid >> 8;
        int n = t * 8 + (lane >> 2);
        int k0 = c * 16 + (lane & 3) * 2;
        const float* wr = Wg + (size_t)n * 2048 + k0;
        uint4 v;
        split_pair(wr[0] * BSCALE, wr[1] * BSCALE, v.x, v.z);
        split_pair(wr[8] * BSCALE, wr[9] * BSCALE, v.y, v.w);
        g_bfrag[tid] = v;
    }
}

// ---------------------------------------------------------------------------
// Main: 576 blocks x 256 threads (8 warps). Warp = (rg = warp>>1, eg = warp&1):
// rows [rowbase + 32*rg, +32), experts [32*eg, +32). A staged in smem (k32 slabs,
// double buffered); B fragments LDG from the L1/L2-resident table.
// ---------------------------------------------------------------------------
__global__ void __launch_bounds__(256, 2) qcr_main_kernel(
    const float* __restrict__ vis,
    float* __restrict__ out)
{
    // pool aliases: mainloop = A stages (2 x 128 x ASTRIDE floats = 36864B);
    // epilogue = Ls (128 x 65 floats = 33280B)
    __shared__ __align__(16) float pool[2 * 128 * ASTRIDE];
    __shared__ float qrow[64];

    const int tid = threadIdx.x;
    const int warp = tid >> 5;
    const int lane = tid & 31;
    const int grp = lane >> 2;
    const int tig = lane & 3;
    const int rg = warp >> 1;
    const int eg = warp & 1;
    const int rowbase = blockIdx.x * 128;

    if (tid < 64) qrow[tid] = g_qlog[(rowbase / 9216) * 64 + tid];

    const uint32_t poolB = (uint32_t)__cvta_generic_to_shared(pool);
    const float* Ag = vis + (size_t)rowbase * KDIM;
    const uint4* Bf = g_bfrag + lane;

    // cp.async mapping: iteration i: linear = i*256+tid, row = lin>>3, seg16 = lin&7
    const int cprow = tid >> 3;          // + i*32
    const int cpseg = tid & 7;           // 16B units within the 128B slab row

    #define CPSTAGE(s)                                                           \
    do {                                                                         \
        uint32_t _dst = poolB + (uint32_t)(((s) & 1) * 128 * ASTRIDE) * 4u;      \
        const float* _src = Ag + (s) * 32;                                       \
        _Pragma("unroll")                                                        \
        for (int _i = 0; _i < 4; _i++) {                                         \
            int _r = cprow + _i * 32;                                            \
            cp16(_dst + (uint32_t)(_r * ASTRIDE + cpseg * 4) * 4u,               \
                 _src + (size_t)_r * KDIM + cpseg * 4);                          \
        }                                                                        \
        asm volatile("cp.async.commit_group;");                                  \
    } while (0)

    float acc[2][4][4];
    #pragma unroll
    for (int i = 0; i < 2; i++)
        #pragma unroll
        for (int t = 0; t < 4; t++)
            #pragma unroll
            for (int j = 0; j < 4; j++) acc[i][t][j] = 0.f;

    CPSTAGE(0);

    #pragma unroll 1
    for (int s = 0; s < NSTAGE; s++) {
        if (s + 1 < NSTAGE) {
            CPSTAGE(s + 1);
            asm volatile("cp.async.wait_group 1;");
        } else {
            asm volatile("cp.async.wait_group 0;");
        }
        __syncthreads();

        const float* As = pool + (s & 1) * 128 * ASTRIDE;

        #pragma unroll
        for (int cc = 0; cc < 2; cc++) {
            const int c = s * 2 + cc;   // global k16 chunk

            // A fragments: mtile i (rows 32rg+16i+{grp,grp+8}), k pairs tig, tig+4
            uint32_t ah[2][4], al[2][4];
            #pragma unroll
            for (int i = 0; i < 2; i++) {
                #pragma unroll
                for (int h = 0; h < 2; h++) {
                    const float* rp = As + (32 * rg + 16 * i + 8 * h + grp) * ASTRIDE
                                      + cc * 16 + 2 * tig;
                    float2 v0 = *reinterpret_cast<const float2*>(rp);       // k01
                    float2 v1 = *reinterpret_cast<const float2*>(rp + 8);   // k89
                    split_pair(v0.x * ASCALE, v0.y * ASCALE, ah[i][h], al[i][h]);
                    split_pair(v1.x * ASCALE, v1.y * ASCALE, ah[i][h + 2], al[i][h + 2]);
                }
            }

            #pragma unroll
            for (int t = 0; t < 4; t++) {
                uint4 b = Bf[(c * 8 + eg * 4 + t) * 32];
                #pragma unroll
                for (int i = 0; i < 2; i++) {
                    mma16816(acc[i][t], ah[i][0], ah[i][1], ah[i][2], ah[i][3], b.x, b.y);
                    mma16816(acc[i][t], ah[i][0], ah[i][1], ah[i][2], ah[i][3], b.z, b.w);
                    mma16816(acc[i][t], al[i][0], al[i][1], al[i][2], al[i][3], b.x, b.y);
                }
            }
        }
        __syncthreads();
    }

    // ---- stage logits to smem (pool reused as Ls[128][65]) ----
    float* Ls = pool;
    #pragma unroll
    for (int i = 0; i < 2; i++) {
        const int rl0 = 32 * rg + 16 * i + grp;
        #pragma unroll
        for (int t = 0; t < 4; t++) {
            int col = eg * 32 + t * 8 + tig * 2;
            float q0 = qrow[col], q1 = qrow[col + 1];
            Ls[rl0 * 65 + col]           = acc[i][t][0] * OSCALE + q0;
            Ls[rl0 * 65 + col + 1]       = acc[i][t][1] * OSCALE + q1;
            Ls[(rl0 + 8) * 65 + col]     = acc[i][t][2] * OSCALE + q0;
            Ls[(rl0 + 8) * 65 + col + 1] = acc[i][t][3] * OSCALE + q1;
        }
    }
    __syncthreads();

    // ---- per-row softmax + top-2 + outputs (threads 0..127 = rows) ----
    const size_t O_TI = 2 * (size_t)MROWS;
    const size_t O_SC = 4 * (size_t)MROWS;
    const size_t O_LG = O_SC + (size_t)MROWS * NEXP;

    if (tid < 128) {
        float d[64];
        const float* Lr = Ls + tid * 65;
        #pragma unroll
        for (int e = 0; e < 64; e++) d[e] = Lr[e];

        float m1 = -1e30f, m2 = -1e30f;
        int i1 = 0, i2 = 0;
        #pragma unroll
        for (int e = 0; e < 64; e++) {
            float v = d[e];
            if (v > m1) { m2 = m1; i2 = i1; m1 = v; i1 = e; }
            else if (v > m2) { m2 = v; i2 = e; }
        }
        float ssum = 0.f;
        #pragma unroll
        for (int e = 0; e < 64; e++) ssum += __expf(d[e] - m1);
        float inv = 1.0f / ssum;

        size_t g = (size_t)(rowbase + tid);
        out[g * 2 + 0] = inv;
        out[g * 2 + 1] = __expf(m2 - m1) * inv;
        out[O_TI + g * 2 + 0] = (float)i1;
        out[O_TI + g * 2 + 1] = (float)i2;

        float4* sc = reinterpret_cast<float4*>(out + O_SC + g * 64);
        float4* lg = reinterpret_cast<float4*>(out + O_LG + g * 64);
        #pragma unroll
        for (int e4 = 0; e4 < 16; e4++) {
            float4 lv = make_float4(d[e4 * 4], d[e4 * 4 + 1], d[e4 * 4 + 2], d[e4 * 4 + 3]);
            lg[e4] = lv;
            sc[e4] = make_float4(__expf(lv.x - m1) * inv, __expf(lv.y - m1) * inv,
                                 __expf(lv.z - m1) * inv, __expf(lv.w - m1) * inv);
        }
    }
}

// ---------------------------------------------------------------------------
extern "C" void kernel_launch(void* const* d_in, const int* in_sizes, int n_in,
                              void* d_out, int out_size)
{
    const float* vis = (const float*)d_in[0];
    const float* qry = (const float*)d_in[1];
    const float* Wg  = (const float*)d_in[2];
    float* out = (float*)d_out;

    qcr_prep_kernel<<<64, 256>>>(qry, Wg);
    qcr_main_kernel<<<NBLOCKS, 256>>>(vis, out);
}

// round 6
// speedup vs baseline: 1.4940x; 1.4534x over previous
#include <cuda_runtime.h>
#include <cuda_fp16.h>
#include <cstdint>

// QueryConditionedRouter via mma.sync (HMMA) fp16 2-term split, 3 passes.
// R6 = R3 skeleton (warp-autonomous, no mainloop barriers) + k-permutation:
//   B fragments are pre-packed with actual-k = {4tig..4tig+3} in the logical
//   slots {2tig,2tig+1,2tig+8,2tig+9}, so A fragments come from ONE LDG.128
//   per row-group per chunk (A L1 wavefronts halved vs R3).
//   vis_emb  : (128, 576, 1024) f32  -> M = 73728 rows, K = 1024
//   query_emb: (8, 1024) f32
//   W_gate   : (64, 2048) f32
// Output (concat f32): topk_scores (M,2) | topk_idx (M,2) | gate_scores (M,64) | gate_logits (M,64)

#define MROWS   73728
#define KDIM    1024
#define NEXP    64
#define NBLOCKS (MROWS / 128)       // 576
#define ASCALE  4096.0f             // 2^12
#define BSCALE  32.0f               // 2^5
#define OSCALE  7.62939453125e-06f  // 2^-17

__device__ float g_qlog[512];
// B fragments, fragment-major: entry = ((chunk*8 + ntile)*32 + lane)
//   uint4 = { hi(k0,k1), hi(k2,k3), lo(k0,k1), lo(k2,k3) } with k = chunk*16 + 4*tig
//   (k-permuted so A side can use contiguous float4 loads)
__device__ uint4 g_bfrag[64 * 8 * 32];

__device__ __forceinline__ void split_pair(float f0, float f1, uint32_t &h, uint32_t &l) {
    __half2 hh = __floats2half2_rn(f0, f1);
    float g0 = __low2float(hh), g1 = __high2float(hh);
    __half2 ll = __floats2half2_rn(f0 - g0, f1 - g1);
    h = *reinterpret_cast<uint32_t*>(&hh);
    l = *reinterpret_cast<uint32_t*>(&ll);
}

__device__ __forceinline__ void mma16816(float* c, uint32_t a0, uint32_t a1, uint32_t a2,
                                         uint32_t a3, uint32_t b0, uint32_t b1) {
    asm volatile(
        "mma.sync.aligned.m16n8k16.row.col.f32.f16.f16.f32 "
        "{%0,%1,%2,%3}, {%4,%5,%6,%7}, {%8,%9}, {%0,%1,%2,%3};"
        : "+f"(c[0]), "+f"(c[1]), "+f"(c[2]), "+f"(c[3])
        : "r"(a0), "r"(a1), "r"(a2), "r"(a3), "r"(b0), "r"(b1));
}

// ---------------------------------------------------------------------------
// Prep: (a) qry logits (one warp per (b,e)); (b) k-permuted B fragment build.
// ---------------------------------------------------------------------------
__global__ void qcr_prep_kernel(const float* __restrict__ qry, const float* __restrict__ Wg) {
    const int tid = blockIdx.x * 256 + threadIdx.x;
    {
        int w = tid >> 5, lane = tid & 31;
        const float* qp = qry + (size_t)(w >> 6) * KDIM;
        const float* wp = Wg + (size_t)(w & 63) * 2048 + 1024;
        float acc = 0.f;
        #pragma unroll 8
        for (int i = lane; i < KDIM; i += 32) acc += qp[i] * wp[i];
        #pragma unroll
        for (int o = 16; o; o >>= 1) acc += __shfl_xor_sync(0xffffffffu, acc, o);
        if (lane == 0) g_qlog[w] = acc;
    }
    {
        int lane = tid & 31;
        int t = (tid >> 5) & 7;           // n8 tile
        int c = tid >> 8;                 // k16 chunk
        int n = t * 8 + (lane >> 2);
        int k0 = c * 16 + (lane & 3) * 4; // permuted: contiguous 4 k per lane
        const float* wr = Wg + (size_t)n * 2048 + k0;
        float w0 = wr[0] * BSCALE, w1 = wr[1] * BSCALE;
        float w2 = wr[2] * BSCALE, w3 = wr[3] * BSCALE;
        uint4 v;
        split_pair(w0, w1, v.x, v.z);
        split_pair(w2, w3, v.y, v.w);
        g_bfrag[tid] = v;
    }
}

// ---------------------------------------------------------------------------
// Main: 576 blocks x 256 threads (8 warps). Warp w: rows [rowbase+16w, +16),
// all 64 experts. A via one float4 LDG per row-group per chunk (k-permuted).
// ---------------------------------------------------------------------------
__global__ void __launch_bounds__(256, 2) qcr_main_kernel(
    const float* __restrict__ vis,
    float* __restrict__ out)
{
    __shared__ float Ls[128 * 65];
    __shared__ float qrow[64];

    const int tid = threadIdx.x;
    const int warp = tid >> 5;
    const int lane = tid & 31;
    const int grp = lane >> 2;        // 0..7
    const int tig = lane & 3;         // 0..3
    const int rowbase = blockIdx.x * 128;

    if (tid < 64) qrow[tid] = g_qlog[(rowbase / 9216) * 64 + tid];

    const int r0 = rowbase + warp * 16 + grp;
    const float4* A0 = reinterpret_cast<const float4*>(vis + (size_t)r0 * KDIM) + tig;
    const float4* A1 = reinterpret_cast<const float4*>(vis + (size_t)(r0 + 8) * KDIM) + tig;
    const uint4* Bf = g_bfrag + lane;

    float acc[8][4];
    #pragma unroll
    for (int t = 0; t < 8; t++)
        #pragma unroll
        for (int j = 0; j < 4; j++) acc[t][j] = 0.f;

    #pragma unroll 2
    for (int c = 0; c < 64; c++) {
        // A fragment: rows (r0, r0+8), actual k = c*16 + 4tig .. +3  (permuted slots)
        float4 q0 = A0[c * 4];
        float4 q1 = A1[c * 4];

        uint32_t ah[4], al[4];
        split_pair(q0.x * ASCALE, q0.y * ASCALE, ah[0], al[0]);   // a0: row r0,   k01
        split_pair(q1.x * ASCALE, q1.y * ASCALE, ah[1], al[1]);   // a1: row r0+8, k01
        split_pair(q0.z * ASCALE, q0.w * ASCALE, ah[2], al[2]);   // a2: row r0,   k23
        split_pair(q1.z * ASCALE, q1.w * ASCALE, ah[3], al[3]);   // a3: row r0+8, k23

        #pragma unroll
        for (int t = 0; t < 8; t++) {
            uint4 b = Bf[(c * 8 + t) * 32];
            mma16816(acc[t], ah[0], ah[1], ah[2], ah[3], b.x, b.y);   // Ahi * Bhi
            mma16816(acc[t], ah[0], ah[1], ah[2], ah[3], b.z, b.w);   // Ahi * Blo
            mma16816(acc[t], al[0], al[1], al[2], al[3], b.x, b.y);   // Alo * Bhi
        }
    }

    // ---- stage logits to smem (rescale + add query logits) ----
    {
        const int rl0 = warp * 16 + grp;
        #pragma unroll
        for (int t = 0; t < 8; t++) {
            int col = t * 8 + tig * 2;
            float q0 = qrow[col], q1 = qrow[col + 1];
            Ls[rl0 * 65 + col]           = acc[t][0] * OSCALE + q0;
            Ls[rl0 * 65 + col + 1]       = acc[t][1] * OSCALE + q1;
            Ls[(rl0 + 8) * 65 + col]     = acc[t][2] * OSCALE + q0;
            Ls[(rl0 + 8) * 65 + col + 1] = acc[t][3] * OSCALE + q1;
        }
    }
    __syncthreads();

    // ---- per-row softmax + top-2 + outputs ----
    const size_t O_TI = 2 * (size_t)MROWS;
    const size_t O_SC = 4 * (size_t)MROWS;
    const size_t O_LG = O_SC + (size_t)MROWS * NEXP;

    if (tid < 128) {
        float d[64];
        const float* Lr = Ls + tid * 65;
        #pragma unroll
        for (int e = 0; e < 64; e++) d[e] = Lr[e];

        float m1 = -1e30f, m2 = -1e30f;
        int i1 = 0, i2 = 0;
        #pragma unroll
        for (int e = 0; e < 64; e++) {
            float v = d[e];
            if (v > m1) { m2 = m1; i2 = i1; m1 = v; i1 = e; }
            else if (v > m2) { m2 = v; i2 = e; }
        }
        float ssum = 0.f;
        #pragma unroll
        for (int e = 0; e < 64; e++) ssum += __expf(d[e] - m1);
        float inv = 1.0f / ssum;

        size_t g = (size_t)(rowbase + tid);
        out[g * 2 + 0] = inv;
        out[g * 2 + 1] = __expf(m2 - m1) * inv;
        out[O_TI + g * 2 + 0] = (float)i1;
        out[O_TI + g * 2 + 1] = (float)i2;

        float4* sc = reinterpret_cast<float4*>(out + O_SC + g * 64);
        float4* lg = reinterpret_cast<float4*>(out + O_LG + g * 64);
        #pragma unroll
        for (int e4 = 0; e4 < 16; e4++) {
            float4 lv = make_float4(d[e4 * 4], d[e4 * 4 + 1], d[e4 * 4 + 2], d[e4 * 4 + 3]);
            lg[e4] = lv;
            sc[e4] = make_float4(__expf(lv.x - m1) * inv, __expf(lv.y - m1) * inv,
                                 __expf(lv.z - m1) * inv, __expf(lv.w - m1) * inv);
        }
    }
}

// ---------------------------------------------------------------------------
extern "C" void kernel_launch(void* const* d_in, const int* in_sizes, int n_in,
                              void* d_out, int out_size)
{
    const float* vis = (const float*)d_in[0];
    const float* qry = (const float*)d_in[1];
    const float* Wg  = (const float*)d_in[2];
    float* out = (float*)d_out;

    qcr_prep_kernel<<<64, 256>>>(qry, Wg);
    qcr_main_kernel<<<NBLOCKS, 256>>>(vis, out);
}